// round 11
// baseline (speedup 1.0000x reference)
#include <cuda_runtime.h>
#include <cstdint>

// Problem constants
#define TOK    8192
#define EMB_   768
#define NQKV   2304
#define HEADS_ 8
#define HDIM   96
#define SEQ    2048
#define BATCH  4

// log2(e)/sqrt(768): folded into q so softmax is a bare ex2.approx
#define SCALE_Q 0.05205875899635608f

// ---------------- scratch (static device globals) ---------------------------
__device__ float g_xr[TOK * EMB_];        // tf32-rounded x
__device__ float g_w1[EMB_ * NQKV];       // permuted+rounded Wqkv
__device__ float g_b1[NQKV];              // permuted bqkv
__device__ float g_w2[EMB_ * EMB_];       // rounded Wproj
__device__ float g_qkv[3 * TOK * EMB_];   // q/k/v planes (b,n,h,d)
__device__ float g_ctx[TOK * EMB_];       // attention out

// ---------------- helpers ---------------------------------------------------
__device__ __forceinline__ float tf32r(float x) {
    unsigned u;
    asm("cvt.rna.tf32.f32 %0, %1;" : "=r"(u) : "f"(x));
    return __uint_as_float(u);
}
__device__ __forceinline__ float ex2f(float x) {
    float y;
    asm("ex2.approx.f32 %0, %1;" : "=f"(y) : "f"(x));
    return y;
}
__device__ __forceinline__ void cpa16(uint32_t dst, const float* src) {
    asm volatile("cp.async.cg.shared.global [%0], [%1], 16;" :: "r"(dst), "l"(src));
}
#define CP_COMMIT() asm volatile("cp.async.commit_group;")
#define CP_WAIT(n)  asm volatile("cp.async.wait_group %0;" :: "n"(n))

// D += A(16x8,row) * B(8x8,col), tf32 in / f32 acc
__device__ __forceinline__ void mma8(float c[4], const unsigned a[4], const unsigned b[2]) {
    asm volatile(
        "mma.sync.aligned.m16n8k8.row.col.f32.tf32.tf32.f32 "
        "{%0,%1,%2,%3}, {%4,%5,%6,%7}, {%8,%9}, {%0,%1,%2,%3};"
        : "+f"(c[0]), "+f"(c[1]), "+f"(c[2]), "+f"(c[3])
        : "r"(a[0]), "r"(a[1]), "r"(a[2]), "r"(a[3]), "r"(b[0]), "r"(b[1]));
}

// ---------------- prep kernels ----------------------------------------------
__global__ void round4_k(const float4* __restrict__ s, float4* __restrict__ d, int n4) {
    int i = blockIdx.x * 256 + threadIdx.x;
    if (i < n4) {
        float4 v = s[i];
        v.x = tf32r(v.x); v.y = tf32r(v.y); v.z = tf32r(v.z); v.w = tf32r(v.w);
        d[i] = v;
    }
}

// permute Wqkv cols (h d qkv) -> (qkv h d), round; also permute bias
__global__ void permw_k(const float* __restrict__ W, const float* __restrict__ bias) {
    int gid = blockIdx.x * 256 + threadIdx.x;
    if (gid < EMB_ * NQKV / 4) {
        int o4 = gid * 4;
        int k = o4 / NQKV, j = o4 - k * NQKV;
        int qkv = j / 768, hd = j - qkv * 768;
        const float* src = W + (size_t)k * NQKV + qkv;
        float4 v;
        v.x = tf32r(src[(hd + 0) * 3]);
        v.y = tf32r(src[(hd + 1) * 3]);
        v.z = tf32r(src[(hd + 2) * 3]);
        v.w = tf32r(src[(hd + 3) * 3]);
        *(float4*)(g_w1 + o4) = v;
    }
    if (gid < NQKV) {
        int qkv = gid / 768, hd = gid - qkv * 768;
        g_b1[gid] = bias[hd * 3 + qkv];
    }
}

// -- tf32 GEMM: 128x128 block, 256 thr / 8 warps @ 32x64 tiles, 2 CTA/SM -----
#define BM  128
#define BN  128
#define BK  32
#define LDA 36      // 36 % 32 == 4 -> conflict-free A frags
#define LDB 136     // 136 % 32 == 8 -> conflict-free B frags
#define STG 3
#define STAGE_F (BM * LDA + BK * LDB)   // 8960 floats / stage (35840 B)

__device__ __forceinline__ void gemm_issue(
    uint32_t smb, const float* __restrict__ A, const float* __restrict__ W,
    int bm, int bn, int K, int N, int tid, int kt)
{
    const int k0 = kt * BK;
    const uint32_t sb = smb + (uint32_t)((kt % STG) * STAGE_F) * 4u;
#pragma unroll
    for (int i = 0; i < 4; i++) {               // A: 128 rows x 8 chunks = 1024
        int id = tid + 256 * i, r = id >> 3, c = id & 7;
        cpa16(sb + (uint32_t)(r * LDA + c * 4) * 4u,
              A + (size_t)(bm + r) * K + k0 + c * 4);
    }
    const uint32_t sbB = sb + (uint32_t)(BM * LDA) * 4u;
#pragma unroll
    for (int i = 0; i < 4; i++) {               // B: 32 rows x 32 chunks = 1024
        int id = tid + 256 * i, kr = id >> 5, c = id & 31;
        cpa16(sbB + (uint32_t)(kr * LDB + c * 4) * 4u,
              W + (size_t)(k0 + kr) * N + bn + c * 4);
    }
    CP_COMMIT();
}

__global__ __launch_bounds__(256, 2) void gemm_tf32(
    const float* __restrict__ A, const float* __restrict__ W,
    const float* __restrict__ bias, float* __restrict__ C,
    int M, int N, int K, int qkv_mode)
{
    extern __shared__ float sm[];
    const uint32_t smb = (uint32_t)__cvta_generic_to_shared(sm);

    const int bm = blockIdx.y * BM, bn = blockIdx.x * BN;
    const int tid = threadIdx.x;
    const int w = tid >> 5, lane = tid & 31, lq = lane >> 2, lr = lane & 3;
    const int wm = (w & 3) * 32, wn = (w >> 2) * 64;   // 4 m-warps x 2 n-warps

    float acc[2][8][4];
#pragma unroll
    for (int i = 0; i < 2; i++)
#pragma unroll
        for (int j = 0; j < 8; j++)
#pragma unroll
            for (int q = 0; q < 4; q++) acc[i][j][q] = 0.f;

    gemm_issue(smb, A, W, bm, bn, K, N, tid, 0);
    gemm_issue(smb, A, W, bm, bn, K, N, tid, 1);

    const int nkt = K / BK;
    for (int kt = 0; kt < nkt; ++kt) {
        if (kt + 1 < nkt) { CP_WAIT(1); } else { CP_WAIT(0); }
        __syncthreads();
        if (kt + 2 < nkt) gemm_issue(smb, A, W, bm, bn, K, N, tid, kt + 2);

        const float* cA = sm + (kt % STG) * STAGE_F;
        const float* cB = cA + BM * LDA;

#pragma unroll
        for (int kk = 0; kk < 4; kk++) {
            const int k8 = kk * 8;
            unsigned af[2][4];
#pragma unroll
            for (int mi = 0; mi < 2; mi++) {
                int r = wm + mi * 16;
                af[mi][0] = __float_as_uint(cA[(r + lq) * LDA + k8 + lr]);
                af[mi][1] = __float_as_uint(cA[(r + 8 + lq) * LDA + k8 + lr]);
                af[mi][2] = __float_as_uint(cA[(r + lq) * LDA + k8 + lr + 4]);
                af[mi][3] = __float_as_uint(cA[(r + 8 + lq) * LDA + k8 + lr + 4]);
            }
#pragma unroll
            for (int ni = 0; ni < 8; ni++) {
                unsigned bf[2];
                int c = wn + ni * 8 + lq;
                bf[0] = __float_as_uint(cB[(k8 + lr) * LDB + c]);
                bf[1] = __float_as_uint(cB[(k8 + lr + 4) * LDB + c]);
                mma8(acc[0][ni], af[0], bf);
                mma8(acc[1][ni], af[1], bf);
            }
        }
    }

    if (qkv_mode) {
        // scatter into q/k/v planes; round tf32; scale q by log2e/sqrt(768)
#pragma unroll
        for (int ni = 0; ni < 8; ni++) {
            int j = bn + wn + ni * 8 + 2 * lr;
            int qkv = j / 768, pc = j - qkv * 768;
            float sc = (qkv == 0) ? SCALE_Q : 1.f;
            float b0 = bias[j], b1 = bias[j + 1];
            float* dst = C + (size_t)qkv * TOK * EMB_;
#pragma unroll
            for (int mi = 0; mi < 2; mi++) {
                int t = bm + wm + mi * 16 + lq;
                float2 v0 = make_float2(tf32r((acc[mi][ni][0] + b0) * sc),
                                        tf32r((acc[mi][ni][1] + b1) * sc));
                float2 v1 = make_float2(tf32r((acc[mi][ni][2] + b0) * sc),
                                        tf32r((acc[mi][ni][3] + b1) * sc));
                *(float2*)(dst + (size_t)t * EMB_ + pc) = v0;
                *(float2*)(dst + (size_t)(t + 8) * EMB_ + pc) = v1;
            }
        }
    } else {
#pragma unroll
        for (int ni = 0; ni < 8; ni++) {
            int col = bn + wn + ni * 8 + 2 * lr;
            float b0 = bias[col], b1 = bias[col + 1];
#pragma unroll
            for (int mi = 0; mi < 2; mi++) {
                int r0 = bm + wm + mi * 16 + lq;
                *(float2*)(C + (size_t)r0 * N + col) =
                    make_float2(acc[mi][ni][0] + b0, acc[mi][ni][1] + b1);
                *(float2*)(C + (size_t)(r0 + 8) * N + col) =
                    make_float2(acc[mi][ni][2] + b0, acc[mi][ni][3] + b1);
            }
        }
    }
}

// -- attention: FA2-style, 16 warp-private rows/warp, 256 thr, 2 CTA/SM ------
#define AQ   128
#define AK   32
#define LQS  100
#define LKS  100
#define LVS  104
#define OFF_K 12800                       // sQ = 128*100
#define OFF_V (OFF_K + 2 * AK * LKS)      // 12800 + 6400  = 19200
#define ATT_F (OFF_V + 2 * AK * LVS)      // 19200 + 6656  = 25856 fl (103424 B)
#define NIT (SEQ / AK)                    // 64

// K tile: 32 rows x 24 float4 = 768 chunks; V same; 1536 over 256 thr = 6.
__device__ __forceinline__ void attn_issue(
    uint32_t smb, const float* __restrict__ Kg, const float* __restrict__ Vg,
    int tid, int it)
{
    const int base_n = it * AK;
    const int buf = it & 1;
#pragma unroll
    for (int i = 0; i < 6; i++) {
        int id = tid + 256 * i;
        if (id < 768) {
            int r = id / 24, c = id - r * 24;
            cpa16(smb + (uint32_t)(OFF_K + buf * (AK * LKS) + r * LKS + c * 4) * 4u,
                  Kg + (size_t)(base_n + r) * EMB_ + c * 4);
        } else {
            int id2 = id - 768;
            int r = id2 / 24, c = id2 - r * 24;
            cpa16(smb + (uint32_t)(OFF_V + buf * (AK * LVS) + r * LVS + c * 4) * 4u,
                  Vg + (size_t)(base_n + r) * EMB_ + c * 4);
        }
    }
}

__global__ __launch_bounds__(256, 2) void attn3() {
    extern __shared__ float sm[];
    const uint32_t smb = (uint32_t)__cvta_generic_to_shared(sm);

    const int bh = blockIdx.y;
    const int qb = blockIdx.x * AQ;
    const int b = bh >> 3, h = bh & 7;
    const int tid = threadIdx.x, w = tid >> 5, lane = tid & 31;
    const int lq = lane >> 2, lr = lane & 3;
    const int wr = w * 16;                 // warp-private row base (16 rows)

    const float* Qg = g_qkv + (size_t)(b * SEQ + qb) * EMB_ + h * HDIM;
    const float* Kg = g_qkv + (size_t)TOK * EMB_ + (size_t)(b * SEQ) * EMB_ + h * HDIM;
    const float* Vg = Kg + (size_t)TOK * EMB_;

    // prologue: Q tile (128 rows x 24 chunks = 3072 = 12*256) + KV stage 0
#pragma unroll
    for (int i = 0; i < 12; i++) {
        int id = tid + 256 * i;
        int r = id / 24, c = id - r * 24;
        cpa16(smb + (uint32_t)(r * LQS + c * 4) * 4u, Qg + (size_t)r * EMB_ + c * 4);
    }
    attn_issue(smb, Kg, Vg, tid, 0);
    CP_COMMIT();

    float o[12][4];
#pragma unroll
    for (int j = 0; j < 12; j++)
#pragma unroll
        for (int q = 0; q < 4; q++) o[j][q] = 0.f;
    float rs[2] = {0.f, 0.f};

    const unsigned src01 = (lane & 28) | (lr >> 1);   // 4*lq + lr/2
    const unsigned src23 = src01 + 2;
    const bool odd = (lr & 1);

    for (int it = 0; it < NIT; ++it) {
        CP_WAIT(0);
        __syncthreads();
        if (it + 1 < NIT) { attn_issue(smb, Kg, Vg, tid, it + 1); CP_COMMIT(); }

        const float* cK = sm + OFF_K + (it & 1) * (AK * LKS);
        const float* cV = sm + OFF_V + (it & 1) * (AK * LVS);

        // S[16x32] per warp = Q @ K^T
        float s[4][4];
#pragma unroll
        for (int j = 0; j < 4; j++)
#pragma unroll
            for (int q = 0; q < 4; q++) s[j][q] = 0.f;

#pragma unroll
        for (int kk = 0; kk < 12; kk++) {
            int k8 = kk * 8;
            unsigned af[4];
            af[0] = __float_as_uint(sm[(wr + lq) * LQS + k8 + lr]);
            af[1] = __float_as_uint(sm[(wr + 8 + lq) * LQS + k8 + lr]);
            af[2] = __float_as_uint(sm[(wr + lq) * LQS + k8 + lr + 4]);
            af[3] = __float_as_uint(sm[(wr + 8 + lq) * LQS + k8 + lr + 4]);
#pragma unroll
            for (int ni = 0; ni < 4; ni++) {
                unsigned bf[2];
                int c = ni * 8 + lq;
                bf[0] = __float_as_uint(cK[c * LKS + k8 + lr]);
                bf[1] = __float_as_uint(cK[c * LKS + k8 + lr + 4]);
                mma8(s[ni], af, bf);
            }
        }

        // P = tf32(2^S) in-place; lane-partial row sums
#pragma unroll
        for (int ni = 0; ni < 4; ni++) {
            float p0 = tf32r(ex2f(s[ni][0]));
            float p1 = tf32r(ex2f(s[ni][1]));
            float p2 = tf32r(ex2f(s[ni][2]));
            float p3 = tf32r(ex2f(s[ni][3]));
            s[ni][0] = p0; s[ni][1] = p1; s[ni][2] = p2; s[ni][3] = p3;
            rs[0] += p0 + p1;
            rs[1] += p2 + p3;
        }

        // O += P @ V : A-frags built from S c-frags via shuffles
#pragma unroll
        for (int j = 0; j < 4; j++) {
            unsigned af[4];
            {
                float x, y;
                x = __shfl_sync(0xffffffffu, s[j][0], src01);
                y = __shfl_sync(0xffffffffu, s[j][1], src01);
                af[0] = __float_as_uint(odd ? y : x);
                x = __shfl_sync(0xffffffffu, s[j][2], src01);
                y = __shfl_sync(0xffffffffu, s[j][3], src01);
                af[1] = __float_as_uint(odd ? y : x);
                x = __shfl_sync(0xffffffffu, s[j][0], src23);
                y = __shfl_sync(0xffffffffu, s[j][1], src23);
                af[2] = __float_as_uint(odd ? y : x);
                x = __shfl_sync(0xffffffffu, s[j][2], src23);
                y = __shfl_sync(0xffffffffu, s[j][3], src23);
                af[3] = __float_as_uint(odd ? y : x);
            }
            const int k8 = j * 8;
#pragma unroll
            for (int ni = 0; ni < 12; ni++) {
                unsigned bf[2];
                int c = ni * 8 + lq;
                bf[0] = __float_as_uint(cV[(k8 + lr) * LVS + c]);
                bf[1] = __float_as_uint(cV[(k8 + lr + 4) * LVS + c]);
                mma8(o[ni], af, bf);
            }
        }
    }

    // quad-reduce row sums (cols partitioned over lr within each quad)
#pragma unroll
    for (int half = 0; half < 2; half++) {
        float v = rs[half];
        v += __shfl_xor_sync(0xffffffffu, v, 1);
        v += __shfl_xor_sync(0xffffffffu, v, 2);
        rs[half] = v;
    }

    // normalize + tf32-round ctx
    {
        int r0 = wr + lq;
        float inv0 = 1.f / rs[0];
        float inv1 = 1.f / rs[1];
        size_t t0 = (size_t)(b * SEQ + qb + r0) * EMB_ + h * HDIM;
        size_t t1 = (size_t)(b * SEQ + qb + r0 + 8) * EMB_ + h * HDIM;
#pragma unroll
        for (int ni = 0; ni < 12; ni++) {
            int col = ni * 8 + 2 * lr;
            *(float2*)(g_ctx + t0 + col) = make_float2(tf32r(o[ni][0] * inv0),
                                                       tf32r(o[ni][1] * inv0));
            *(float2*)(g_ctx + t1 + col) = make_float2(tf32r(o[ni][2] * inv1),
                                                       tf32r(o[ni][3] * inv1));
        }
    }
}

// ---------------- launch -----------------------------------------------------
extern "C" void kernel_launch(void* const* d_in, const int* in_sizes, int n_in,
                              void* d_out, int out_size) {
    const float* x     = (const float*)d_in[0];
    const float* Wqkv  = (const float*)d_in[1];
    const float* bqkv  = (const float*)d_in[2];
    const float* Wproj = (const float*)d_in[3];
    const float* bproj = (const float*)d_in[4];
    float* out = (float*)d_out;

    void *pxr, *pw1, *pb1, *pw2, *pqkv, *pctx;
    cudaGetSymbolAddress(&pxr, g_xr);
    cudaGetSymbolAddress(&pw1, g_w1);
    cudaGetSymbolAddress(&pb1, g_b1);
    cudaGetSymbolAddress(&pw2, g_w2);
    cudaGetSymbolAddress(&pqkv, g_qkv);
    cudaGetSymbolAddress(&pctx, g_ctx);

    const int gemm_smem = STG * STAGE_F * 4;   // 107520 B -> 2 CTAs/SM (16 warps)
    const int attn_smem = ATT_F * 4;           // 103424 B -> 2 CTAs/SM (16 warps)
    cudaFuncSetAttribute(gemm_tf32, cudaFuncAttributeMaxDynamicSharedMemorySize, gemm_smem);
    cudaFuncSetAttribute(attn3, cudaFuncAttributeMaxDynamicSharedMemorySize, attn_smem);

    // 0) prep
    round4_k<<<(TOK * EMB_ / 4 + 255) / 256, 256>>>((const float4*)x, (float4*)pxr, TOK * EMB_ / 4);
    round4_k<<<(EMB_ * EMB_ / 4 + 255) / 256, 256>>>((const float4*)Wproj, (float4*)pw2, EMB_ * EMB_ / 4);
    permw_k<<<(EMB_ * NQKV / 4 + 255) / 256, 256>>>(Wqkv, bqkv);

    // 1) qkv = x @ Wqkv' + bqkv' -> q/k/v planes (q pre-scaled)
    gemm_tf32<<<dim3(NQKV / BN, TOK / BM), 256, gemm_smem>>>(
        (const float*)pxr, (const float*)pw1, (const float*)pb1, (float*)pqkv,
        TOK, NQKV, EMB_, 1);

    // 2) attention
    attn3<<<dim3(SEQ / AQ, BATCH * HEADS_), 256, attn_smem>>>();

    // 3) out = ctx @ Wproj + bproj
    gemm_tf32<<<dim3(EMB_ / BN, TOK / BM), 256, gemm_smem>>>(
        (const float*)pctx, (const float*)pw2, bproj, out,
        TOK, EMB_, EMB_, 0);
}

// round 13
// speedup vs baseline: 1.9731x; 1.9731x over previous
#include <cuda_runtime.h>
#include <cuda_fp16.h>
#include <cstdint>

// Problem constants
#define TOK    8192
#define EMB_   768
#define NQKV   2304
#define HDIM   96
#define SEQ    2048

// log2(e)/sqrt(768): folded into q so softmax is a bare ex2.approx
#define SCALE_Q 0.05205875899635608f

// ---------------- scratch (static device globals) ---------------------------
__device__ __half g_xh[TOK * EMB_];     // fp16 x
__device__ __half g_w1[NQKV * EMB_];    // permuted+transposed Wqkv  [N][K]
__device__ float  g_b1[NQKV];           // permuted bqkv (fp32)
__device__ __half g_w2[EMB_ * EMB_];    // transposed Wproj [N][K]
__device__ __half g_q[TOK * EMB_];      // [b][tok][h*96+d], pre-scaled
__device__ __half g_k[TOK * EMB_];      // [b][tok][h*96+d]
__device__ __half g_vt[TOK * EMB_];     // transposed: [b][h*96+d][tok]
__device__ __half g_ctx[TOK * EMB_];    // attention out, fp16

// ---------------- helpers ---------------------------------------------------
__device__ __forceinline__ float ex2f(float x) {
    float y;
    asm("ex2.approx.f32 %0, %1;" : "=f"(y) : "f"(x));
    return y;
}
__device__ __forceinline__ unsigned packh(float lo, float hi) {
    unsigned u;
    asm("cvt.rn.f16x2.f32 %0, %1, %2;" : "=r"(u) : "f"(hi), "f"(lo));
    return u;
}
__device__ __forceinline__ void cpa16(uint32_t dst, const void* src) {
    asm volatile("cp.async.cg.shared.global [%0], [%1], 16;" :: "r"(dst), "l"(src));
}
#define CP_COMMIT() asm volatile("cp.async.commit_group;")
#define CP_WAIT(n)  asm volatile("cp.async.wait_group %0;" :: "n"(n))

// D += A(16x16,row) * B(16x8,col), fp16 in / f32 acc
__device__ __forceinline__ void mmah(float c[4], const unsigned a[4], const unsigned b[2]) {
    asm volatile(
        "mma.sync.aligned.m16n8k16.row.col.f32.f16.f16.f32 "
        "{%0,%1,%2,%3}, {%4,%5,%6,%7}, {%8,%9}, {%0,%1,%2,%3};"
        : "+f"(c[0]), "+f"(c[1]), "+f"(c[2]), "+f"(c[3])
        : "r"(a[0]), "r"(a[1]), "r"(a[2]), "r"(a[3]), "r"(b[0]), "r"(b[1]));
}

// ---------------- prep kernels ----------------------------------------------
__global__ void cvth_k(const float4* __restrict__ s, __half2* __restrict__ d, int n4) {
    int i = blockIdx.x * 256 + threadIdx.x;
    if (i < n4) {
        float4 v = s[i];
        d[2 * i + 0] = __floats2half2_rn(v.x, v.y);
        d[2 * i + 1] = __floats2half2_rn(v.z, v.w);
    }
}

// Wqkv: permute cols (h d qkv)->(qkv h d) AND transpose to [N=2304][K=768]
__global__ void permw_k(const float* __restrict__ W, const float* __restrict__ bias) {
    int gid = blockIdx.x * 256 + threadIdx.x;
    if (gid < NQKV * (EMB_ / 4)) {
        int j = gid / 192, k4 = gid - (gid / 192) * 192;
        int qkv = j / 768, hd = j - qkv * 768;
        int sc = hd * 3 + qkv;
        int k = k4 * 4;
        __half2 a = __floats2half2_rn(W[(size_t)(k + 0) * NQKV + sc],
                                      W[(size_t)(k + 1) * NQKV + sc]);
        __half2 b = __floats2half2_rn(W[(size_t)(k + 2) * NQKV + sc],
                                      W[(size_t)(k + 3) * NQKV + sc]);
        *(__half2*)(g_w1 + (size_t)j * EMB_ + k) = a;
        *(__half2*)(g_w1 + (size_t)j * EMB_ + k + 2) = b;
    }
    if (gid < NQKV) {
        int qkv = gid / 768, hd = gid - qkv * 768;
        g_b1[gid] = bias[hd * 3 + qkv];
    }
}

// Wproj: transpose to [N][K]
__global__ void transw2_k(const float* __restrict__ W) {
    int gid = blockIdx.x * 256 + threadIdx.x;
    if (gid < EMB_ * (EMB_ / 4)) {
        int n = gid / 192, k4 = gid - (gid / 192) * 192;
        int k = k4 * 4;
        __half2 a = __floats2half2_rn(W[(size_t)(k + 0) * EMB_ + n],
                                      W[(size_t)(k + 1) * EMB_ + n]);
        __half2 b = __floats2half2_rn(W[(size_t)(k + 2) * EMB_ + n],
                                      W[(size_t)(k + 3) * EMB_ + n]);
        *(__half2*)(g_w2 + (size_t)n * EMB_ + k) = a;
        *(__half2*)(g_w2 + (size_t)n * EMB_ + k + 2) = b;
    }
}

// ------- fp16 GEMM: C[M,N] = A[M,768] @ Wt[N,768]^T + b ---------------------
// 128x128 block, 128 thr / 4 warps @ 64x64 tiles, BK=32 halves, 3-stage.
#define BM  128
#define BN  128
#define BKH 32
#define LDA32 20          // words/row: 16 data + 4 pad (20 = 4*odd mod 32)
#define LDB32 20
#define STG 3
#define STW (BM * LDA32 + BM * LDB32)   // 5120 words / stage
#define NKT (EMB_ / BKH)                // 24

__device__ __forceinline__ void gemm_issue(
    uint32_t smb, const __half* __restrict__ A, const __half* __restrict__ Wt,
    int bm, int bn, int tid, int kt)
{
    const int k0 = kt * BKH;
    const uint32_t sb = smb + (uint32_t)((kt % STG) * STW) * 4u;
#pragma unroll
    for (int i = 0; i < 4; i++) {               // A: 128 rows x 4 x 16B
        int id = tid + 128 * i, r = id >> 2, c4 = id & 3;
        cpa16(sb + (uint32_t)(r * LDA32 + c4 * 4) * 4u,
              A + (size_t)(bm + r) * EMB_ + k0 + c4 * 8);
    }
    const uint32_t sbB = sb + (uint32_t)(BM * LDA32) * 4u;
#pragma unroll
    for (int i = 0; i < 4; i++) {               // B: 128 rows x 4 x 16B
        int id = tid + 128 * i, r = id >> 2, c4 = id & 3;
        cpa16(sbB + (uint32_t)(r * LDB32 + c4 * 4) * 4u,
              Wt + (size_t)(bn + r) * EMB_ + k0 + c4 * 8);
    }
    CP_COMMIT();
}

__global__ __launch_bounds__(128, 2) void gemm_h(
    const __half* __restrict__ A, const __half* __restrict__ Wt,
    const float* __restrict__ bias, float* __restrict__ Cf, int qkv_mode)
{
    extern __shared__ unsigned smw[];
    const uint32_t smb = (uint32_t)__cvta_generic_to_shared(smw);

    const int bm = blockIdx.y * BM, bn = blockIdx.x * BN;
    const int tid = threadIdx.x;
    const int w = tid >> 5, lane = tid & 31, lq = lane >> 2, lr = lane & 3;
    const int wm = (w & 1) * 64, wn = (w >> 1) * 64;   // 2x2 warps, 64x64 tiles

    float acc[4][8][4];
#pragma unroll
    for (int i = 0; i < 4; i++)
#pragma unroll
        for (int j = 0; j < 8; j++)
#pragma unroll
            for (int q = 0; q < 4; q++) acc[i][j][q] = 0.f;

    gemm_issue(smb, A, Wt, bm, bn, tid, 0);
    gemm_issue(smb, A, Wt, bm, bn, tid, 1);

    for (int kt = 0; kt < NKT; ++kt) {
        if (kt + 1 < NKT) { CP_WAIT(1); } else { CP_WAIT(0); }
        __syncthreads();
        if (kt + 2 < NKT) gemm_issue(smb, A, Wt, bm, bn, tid, kt + 2);

        const unsigned* cA = smw + (kt % STG) * STW;
        const unsigned* cB = cA + BM * LDA32;

#pragma unroll
        for (int kk = 0; kk < 2; kk++) {        // 2 x k16 per BK=32
            const int kw = kk * 8;
            unsigned af[4][4];
#pragma unroll
            for (int mi = 0; mi < 4; mi++) {
                int r = wm + mi * 16;
                af[mi][0] = cA[(r + lq) * LDA32 + kw + lr];
                af[mi][1] = cA[(r + 8 + lq) * LDA32 + kw + lr];
                af[mi][2] = cA[(r + lq) * LDA32 + kw + lr + 4];
                af[mi][3] = cA[(r + 8 + lq) * LDA32 + kw + lr + 4];
            }
#pragma unroll
            for (int ni = 0; ni < 8; ni++) {
                unsigned bf[2];
                int c = wn + ni * 8 + lq;
                bf[0] = cB[c * LDB32 + kw + lr];
                bf[1] = cB[c * LDB32 + kw + lr + 4];
#pragma unroll
                for (int mi = 0; mi < 4; mi++)
                    mmah(acc[mi][ni], af[mi], bf);
            }
        }
    }

    // epilogue
#pragma unroll
    for (int ni = 0; ni < 8; ni++) {
        int j = bn + wn + ni * 8 + 2 * lr;
        float b0 = bias[j], b1 = bias[j + 1];
        if (qkv_mode) {
            int plane = j / 768, pc = j - plane * 768;   // whole 128-tile in one plane
#pragma unroll
            for (int mi = 0; mi < 4; mi++) {
                int t = bm + wm + mi * 16 + lq;
#pragma unroll
                for (int hh = 0; hh < 2; hh++) {
                    int tt = t + 8 * hh;
                    float v0 = acc[mi][ni][2 * hh + 0] + b0;
                    float v1 = acc[mi][ni][2 * hh + 1] + b1;
                    if (plane == 0) {
                        *(unsigned*)(g_q + (size_t)tt * EMB_ + pc) =
                            packh(v0 * SCALE_Q, v1 * SCALE_Q);
                    } else if (plane == 1) {
                        *(unsigned*)(g_k + (size_t)tt * EMB_ + pc) = packh(v0, v1);
                    } else {
                        int b = tt >> 11, ntok = tt & 2047;
                        size_t base = ((size_t)b * EMB_ + pc) * SEQ + ntok;
                        g_vt[base] = __float2half_rn(v0);
                        g_vt[base + SEQ] = __float2half_rn(v1);
                    }
                }
            }
        } else {
#pragma unroll
            for (int mi = 0; mi < 4; mi++) {
                int t = bm + wm + mi * 16 + lq;
                *(float2*)(Cf + (size_t)t * EMB_ + j) =
                    make_float2(acc[mi][ni][0] + b0, acc[mi][ni][1] + b1);
                *(float2*)(Cf + (size_t)(t + 8) * EMB_ + j) =
                    make_float2(acc[mi][ni][2] + b0, acc[mi][ni][3] + b1);
            }
        }
    }
}

// -------- attention: fp16 FA2, warp-private 32 rows, zero shuffles ----------
#define AQ   128
#define AKT  64                             // tokens per iter
#define LQ32 52                             // 48 data + 4 pad (52%32=20=4*odd)
#define LK32 52
#define LV32 36                             // 32 data + 4 pad (36%32=4)
#define OFFK 6656                           // sQ = 128*52
#define OFFV (OFFK + 2 * AKT * LK32)        // 6656 + 6656 = 13312
#define ATTW (OFFV + 2 * HDIM * LV32)       // 13312 + 6912 = 20224 w (80896 B)
#define NIT (SEQ / AKT)                     // 32

__device__ __forceinline__ void attn_issue(
    uint32_t smb, const __half* __restrict__ Kg, const __half* __restrict__ Vtg,
    int tid, int it)
{
    const int base = it * AKT;
    const int buf = it & 1;
    const uint32_t kb = smb + (uint32_t)(OFFK + buf * (AKT * LK32)) * 4u;
#pragma unroll
    for (int i = 0; i < 6; i++) {           // K: 64 rows x 12 x 16B
        int id = tid + 128 * i, r = id / 12, c4 = id - r * 12;
        cpa16(kb + (uint32_t)(r * LK32 + c4 * 4) * 4u,
              Kg + (size_t)(base + r) * EMB_ + c4 * 8);
    }
    const uint32_t vb = smb + (uint32_t)(OFFV + buf * (HDIM * LV32)) * 4u;
#pragma unroll
    for (int i = 0; i < 6; i++) {           // Vt: 96 rows x 8 x 16B
        int id = tid + 128 * i, r = id >> 3, c4 = id & 7;
        cpa16(vb + (uint32_t)(r * LV32 + c4 * 4) * 4u,
              Vtg + (size_t)r * SEQ + base + c4 * 8);
    }
    CP_COMMIT();
}

__global__ __launch_bounds__(128, 2) void attn4() {
    extern __shared__ unsigned smw[];
    const uint32_t smb = (uint32_t)__cvta_generic_to_shared(smw);

    const int bh = blockIdx.y;
    const int qb = blockIdx.x * AQ;
    const int b = bh >> 3, h = bh & 7;
    const int tid = threadIdx.x, w = tid >> 5, lane = tid & 31;
    const int lq = lane >> 2, lr = lane & 3;
    const int wr = w * 32;                  // warp-private row base

    const __half* Qg = g_q + (size_t)(b * SEQ + qb) * EMB_ + h * HDIM;
    const __half* Kg = g_k + (size_t)(b * SEQ) * EMB_ + h * HDIM;
    const __half* Vtg = g_vt + ((size_t)b * EMB_ + h * HDIM) * SEQ;

    // prologue: Q tile (128 rows x 12 x 16B = 1536 = 12*128) + KV stage 0
#pragma unroll
    for (int i = 0; i < 12; i++) {
        int id = tid + 128 * i, r = id / 12, c4 = id - r * 12;
        cpa16(smb + (uint32_t)(r * LQ32 + c4 * 4) * 4u,
              Qg + (size_t)r * EMB_ + c4 * 8);
    }
    attn_issue(smb, Kg, Vtg, tid, 0);

    float o[2][12][4];
#pragma unroll
    for (int i = 0; i < 2; i++)
#pragma unroll
        for (int j = 0; j < 12; j++)
#pragma unroll
            for (int q = 0; q < 4; q++) o[i][j][q] = 0.f;
    float rs[2][2] = {{0.f, 0.f}, {0.f, 0.f}};

    for (int it = 0; it < NIT; ++it) {
        CP_WAIT(0);
        __syncthreads();
        if (it + 1 < NIT) attn_issue(smb, Kg, Vtg, tid, it + 1);

        const unsigned* cK = smw + OFFK + (it & 1) * (AKT * LK32);
        const unsigned* cV = smw + OFFV + (it & 1) * (HDIM * LV32);

        // S[32x64] per warp = Q @ K^T  (6 k16 steps over HDIM=96)
        float s[2][8][4];
#pragma unroll
        for (int i = 0; i < 2; i++)
#pragma unroll
            for (int j = 0; j < 8; j++)
#pragma unroll
                for (int q = 0; q < 4; q++) s[i][j][q] = 0.f;

#pragma unroll
        for (int kk = 0; kk < 6; kk++) {
            const int kw = kk * 8;
            unsigned af[2][4];
#pragma unroll
            for (int mi = 0; mi < 2; mi++) {
                int r = wr + mi * 16;
                af[mi][0] = smw[(r + lq) * LQ32 + kw + lr];
                af[mi][1] = smw[(r + 8 + lq) * LQ32 + kw + lr];
                af[mi][2] = smw[(r + lq) * LQ32 + kw + lr + 4];
                af[mi][3] = smw[(r + 8 + lq) * LQ32 + kw + lr + 4];
            }
#pragma unroll
            for (int ni = 0; ni < 8; ni++) {
                unsigned bf[2];
                int c = ni * 8 + lq;
                bf[0] = cK[c * LK32 + kw + lr];
                bf[1] = cK[c * LK32 + kw + lr + 4];
                mmah(s[0][ni], af[0], bf);
                mmah(s[1][ni], af[1], bf);
            }
        }

        // P = fp16(2^S), packed in-place as PV A-frag halves; f32 row sums
        unsigned ph[2][8][2];
#pragma unroll
        for (int mi = 0; mi < 2; mi++)
#pragma unroll
            for (int ni = 0; ni < 8; ni++) {
                unsigned u0 = packh(ex2f(s[mi][ni][0]), ex2f(s[mi][ni][1]));
                unsigned u1 = packh(ex2f(s[mi][ni][2]), ex2f(s[mi][ni][3]));
                ph[mi][ni][0] = u0;
                ph[mi][ni][1] = u1;
                float2 f0 = __half22float2(*(__half2*)&u0);
                float2 f1 = __half22float2(*(__half2*)&u1);
                rs[mi][0] += f0.x + f0.y;
                rs[mi][1] += f1.x + f1.y;
            }

        // O += P @ V : A-frags ARE the packed c-frags (no shuffles)
#pragma unroll
        for (int j = 0; j < 4; j++) {
            unsigned af[2][4];
#pragma unroll
            for (int mi = 0; mi < 2; mi++) {
                af[mi][0] = ph[mi][2 * j][0];
                af[mi][1] = ph[mi][2 * j][1];
                af[mi][2] = ph[mi][2 * j + 1][0];
                af[mi][3] = ph[mi][2 * j + 1][1];
            }
            const int kw = j * 8;
#pragma unroll
            for (int ni = 0; ni < 12; ni++) {
                unsigned bf[2];
                int c = ni * 8 + lq;
                bf[0] = cV[c * LV32 + kw + lr];
                bf[1] = cV[c * LV32 + kw + lr + 4];
                mmah(o[0][ni], af[0], bf);
                mmah(o[1][ni], af[1], bf);
            }
        }
    }

    // quad-reduce row sums (cols partitioned over lr within each quad)
#pragma unroll
    for (int mi = 0; mi < 2; mi++)
#pragma unroll
        for (int half = 0; half < 2; half++) {
            float v = rs[mi][half];
            v += __shfl_xor_sync(0xffffffffu, v, 1);
            v += __shfl_xor_sync(0xffffffffu, v, 2);
            rs[mi][half] = v;
        }

    // normalize, write ctx fp16
#pragma unroll
    for (int mi = 0; mi < 2; mi++) {
        int r0 = wr + mi * 16 + lq;
        float inv0 = 1.f / rs[mi][0];
        float inv1 = 1.f / rs[mi][1];
        size_t t0 = (size_t)(b * SEQ + qb + r0) * EMB_ + h * HDIM;
        size_t t1 = (size_t)(b * SEQ + qb + r0 + 8) * EMB_ + h * HDIM;
#pragma unroll
        for (int ni = 0; ni < 12; ni++) {
            int col = ni * 8 + 2 * lr;
            *(unsigned*)(g_ctx + t0 + col) = packh(o[mi][ni][0] * inv0,
                                                   o[mi][ni][1] * inv0);
            *(unsigned*)(g_ctx + t1 + col) = packh(o[mi][ni][2] * inv1,
                                                   o[mi][ni][3] * inv1);
        }
    }
}

// ---------------- launch -----------------------------------------------------
extern "C" void kernel_launch(void* const* d_in, const int* in_sizes, int n_in,
                              void* d_out, int out_size) {
    const float* x     = (const float*)d_in[0];
    const float* Wqkv  = (const float*)d_in[1];
    const float* bqkv  = (const float*)d_in[2];
    const float* Wproj = (const float*)d_in[3];
    const float* bproj = (const float*)d_in[4];
    float* out = (float*)d_out;

    void *pxh, *pw1, *pb1, *pw2, *pctx;
    cudaGetSymbolAddress(&pxh, g_xh);
    cudaGetSymbolAddress(&pw1, g_w1);
    cudaGetSymbolAddress(&pb1, g_b1);
    cudaGetSymbolAddress(&pw2, g_w2);
    cudaGetSymbolAddress(&pctx, g_ctx);

    const int gemm_smem = STG * STW * 4;   // 61440 B -> 2 CTAs/SM
    const int attn_smem = ATTW * 4;        // 80896 B -> 2 CTAs/SM
    cudaFuncSetAttribute(gemm_h, cudaFuncAttributeMaxDynamicSharedMemorySize, gemm_smem);
    cudaFuncSetAttribute(attn4, cudaFuncAttributeMaxDynamicSharedMemorySize, attn_smem);

    // 0) prep: fp16 conversions (+ weight permute/transpose)
    cvth_k<<<(TOK * EMB_ / 4 + 255) / 256, 256>>>(
        (const float4*)x, (__half2*)pxh, TOK * EMB_ / 4);
    permw_k<<<(NQKV * (EMB_ / 4) + 255) / 256, 256>>>(Wqkv, bqkv);
    transw2_k<<<(EMB_ * (EMB_ / 4) + 255) / 256, 256>>>(Wproj);

    // 1) qkv = x @ Wqkv'^T + bqkv' -> q (scaled), k, v-transposed planes
    gemm_h<<<dim3(NQKV / BN, TOK / BM), 128, gemm_smem>>>(
        (const __half*)pxh, (const __half*)pw1, (const float*)pb1, nullptr, 1);

    // 2) attention -> ctx (fp16)
    attn4<<<dim3(SEQ / AQ, 32), 128, attn_smem>>>();

    // 3) out = ctx @ Wproj^T + bproj (fp32 out)
    gemm_h<<<dim3(EMB_ / BN, TOK / BM), 128, gemm_smem>>>(
        (const __half*)pctx, (const __half*)pw2, bproj, out, 0);
}

// round 14
// speedup vs baseline: 2.1050x; 1.0668x over previous
#include <cuda_runtime.h>
#include <cuda_fp16.h>
#include <cstdint>

// Problem constants
#define TOK    8192
#define EMB_   768
#define NQKV   2304
#define HDIM   96
#define SEQ    2048

// log2(e)/sqrt(768): folded into q so softmax is a bare ex2.approx
#define SCALE_Q 0.05205875899635608f

// ---------------- scratch (static device globals) ---------------------------
__device__ __half g_xh[TOK * EMB_];     // fp16 x
__device__ __half g_w1[NQKV * EMB_];    // permuted+transposed Wqkv  [N][K]
__device__ float  g_b1[NQKV];           // permuted bqkv (fp32)
__device__ __half g_w2[EMB_ * EMB_];    // transposed Wproj [N][K]
__device__ __half g_q[TOK * EMB_];      // [b][tok][h*96+d], pre-scaled
__device__ __half g_k[TOK * EMB_];      // [b][tok][h*96+d]
__device__ __half g_vt[TOK * EMB_];     // transposed: [b][h*96+d][tok]
__device__ __half g_ctx[TOK * EMB_];    // attention out, fp16

// ---------------- helpers ---------------------------------------------------
__device__ __forceinline__ float ex2f(float x) {
    float y;
    asm("ex2.approx.f32 %0, %1;" : "=f"(y) : "f"(x));
    return y;
}
__device__ __forceinline__ unsigned packh(float lo, float hi) {
    unsigned u;
    asm("cvt.rn.f16x2.f32 %0, %1, %2;" : "=r"(u) : "f"(hi), "f"(lo));
    return u;
}
__device__ __forceinline__ void cpa16(uint32_t dst, const void* src) {
    asm volatile("cp.async.cg.shared.global [%0], [%1], 16;" :: "r"(dst), "l"(src));
}
#define CP_COMMIT() asm volatile("cp.async.commit_group;")
#define CP_WAIT(n)  asm volatile("cp.async.wait_group %0;" :: "n"(n))

// D += A(16x16,row) * B(16x8,col), fp16 in / f32 acc
__device__ __forceinline__ void mmah(float c[4], const unsigned a[4], const unsigned b0,
                                     const unsigned b1) {
    asm volatile(
        "mma.sync.aligned.m16n8k16.row.col.f32.f16.f16.f32 "
        "{%0,%1,%2,%3}, {%4,%5,%6,%7}, {%8,%9}, {%0,%1,%2,%3};"
        : "+f"(c[0]), "+f"(c[1]), "+f"(c[2]), "+f"(c[3])
        : "r"(a[0]), "r"(a[1]), "r"(a[2]), "r"(a[3]), "r"(b0), "r"(b1));
}

#define LDSM4(r0, r1, r2, r3, addr) \
    asm volatile("ldmatrix.sync.aligned.m8n8.x4.shared.b16 {%0,%1,%2,%3}, [%4];" \
                 : "=r"(r0), "=r"(r1), "=r"(r2), "=r"(r3) : "r"(addr))

// ---------------- prep kernels ----------------------------------------------
__global__ void cvth_k(const float4* __restrict__ s, __half2* __restrict__ d, int n4) {
    int i = blockIdx.x * 256 + threadIdx.x;
    if (i < n4) {
        float4 v = s[i];
        d[2 * i + 0] = __floats2half2_rn(v.x, v.y);
        d[2 * i + 1] = __floats2half2_rn(v.z, v.w);
    }
}

// Wqkv: permute cols (h d qkv)->(qkv h d) AND transpose to [N=2304][K=768]
__global__ void permw_k(const float* __restrict__ W, const float* __restrict__ bias) {
    int gid = blockIdx.x * 256 + threadIdx.x;
    if (gid < NQKV * (EMB_ / 4)) {
        int j = gid / 192, k4 = gid - (gid / 192) * 192;
        int qkv = j / 768, hd = j - qkv * 768;
        int sc = hd * 3 + qkv;
        int k = k4 * 4;
        __half2 a = __floats2half2_rn(W[(size_t)(k + 0) * NQKV + sc],
                                      W[(size_t)(k + 1) * NQKV + sc]);
        __half2 b = __floats2half2_rn(W[(size_t)(k + 2) * NQKV + sc],
                                      W[(size_t)(k + 3) * NQKV + sc]);
        *(__half2*)(g_w1 + (size_t)j * EMB_ + k) = a;
        *(__half2*)(g_w1 + (size_t)j * EMB_ + k + 2) = b;
    }
    if (gid < NQKV) {
        int qkv = gid / 768, hd = gid - qkv * 768;
        g_b1[gid] = bias[hd * 3 + qkv];
    }
}

// Wproj: transpose to [N][K]
__global__ void transw2_k(const float* __restrict__ W) {
    int gid = blockIdx.x * 256 + threadIdx.x;
    if (gid < EMB_ * (EMB_ / 4)) {
        int n = gid / 192, k4 = gid - (gid / 192) * 192;
        int k = k4 * 4;
        __half2 a = __floats2half2_rn(W[(size_t)(k + 0) * EMB_ + n],
                                      W[(size_t)(k + 1) * EMB_ + n]);
        __half2 b = __floats2half2_rn(W[(size_t)(k + 2) * EMB_ + n],
                                      W[(size_t)(k + 3) * EMB_ + n]);
        *(__half2*)(g_w2 + (size_t)n * EMB_ + k) = a;
        *(__half2*)(g_w2 + (size_t)n * EMB_ + k + 2) = b;
    }
}

// ------- fp16 GEMM: C[M,N] = A[M,768] @ Wt[N,768]^T + b ---------------------
// 128x128 block, 4 warps @ 64x64 tiles, BK=64 halves, 3-stage, LDSM frags.
#define BM  128
#define BN  128
#define BKH 64
#define LD32 36           // words/row: 32 data + 4 pad (36 % 32 == 4)
#define STG 3
#define STW (BM * LD32 * 2)   // 9216 words / stage (36864 B)
#define NKT (EMB_ / BKH)      // 12

__device__ __forceinline__ void gemm_issue(
    uint32_t smb, const __half* __restrict__ A, const __half* __restrict__ Wt,
    int bm, int bn, int tid, int kt)
{
    const int k0 = kt * BKH;
    const uint32_t sb = smb + (uint32_t)((kt % STG) * STW) * 4u;
#pragma unroll
    for (int i = 0; i < 8; i++) {               // A: 128 rows x 8 x 16B
        int id = tid + 128 * i, r = id >> 3, c4 = id & 7;
        cpa16(sb + (uint32_t)(r * LD32 + c4 * 4) * 4u,
              A + (size_t)(bm + r) * EMB_ + k0 + c4 * 8);
    }
    const uint32_t sbB = sb + (uint32_t)(BM * LD32) * 4u;
#pragma unroll
    for (int i = 0; i < 8; i++) {               // B: 128 rows x 8 x 16B
        int id = tid + 128 * i, r = id >> 3, c4 = id & 7;
        cpa16(sbB + (uint32_t)(r * LD32 + c4 * 4) * 4u,
              Wt + (size_t)(bn + r) * EMB_ + k0 + c4 * 8);
    }
    CP_COMMIT();
}

__global__ __launch_bounds__(128, 2) void gemm_h(
    const __half* __restrict__ A, const __half* __restrict__ Wt,
    const float* __restrict__ bias, float* __restrict__ Cf, int qkv_mode)
{
    extern __shared__ unsigned smw[];
    const uint32_t smb = (uint32_t)__cvta_generic_to_shared(smw);

    const int bm = blockIdx.y * BM, bn = blockIdx.x * BN;
    const int tid = threadIdx.x;
    const int w = tid >> 5, lane = tid & 31, lq = lane >> 2, lr = lane & 3;
    const int wm = (w & 1) * 64, wn = (w >> 1) * 64;   // 2x2 warps, 64x64 tiles

    // per-lane LDSM offsets (words)
    const uint32_t offA = ((lane & 7) + ((lane >> 3) & 1) * 8) * LD32 + (lane >> 4) * 4;
    const uint32_t offB = ((lane & 7) + ((lane >> 4) & 1) * 8) * LD32 + ((lane >> 3) & 1) * 4;

    float acc[4][8][4];
#pragma unroll
    for (int i = 0; i < 4; i++)
#pragma unroll
        for (int j = 0; j < 8; j++)
#pragma unroll
            for (int q = 0; q < 4; q++) acc[i][j][q] = 0.f;

    gemm_issue(smb, A, Wt, bm, bn, tid, 0);
    gemm_issue(smb, A, Wt, bm, bn, tid, 1);

    for (int kt = 0; kt < NKT; ++kt) {
        if (kt + 1 < NKT) { CP_WAIT(1); } else { CP_WAIT(0); }
        __syncthreads();
        if (kt + 2 < NKT) gemm_issue(smb, A, Wt, bm, bn, tid, kt + 2);

        const uint32_t sA = smb + (uint32_t)((kt % STG) * STW) * 4u;
        const uint32_t sB = sA + (uint32_t)(BM * LD32) * 4u;

#pragma unroll
        for (int kk = 0; kk < 4; kk++) {        // 4 x k16 per BK=64
            const uint32_t kw = kk * 8;
            unsigned af[4][4];
#pragma unroll
            for (int mi = 0; mi < 4; mi++)
                LDSM4(af[mi][0], af[mi][1], af[mi][2], af[mi][3],
                      sA + ((uint32_t)((wm + mi * 16) * LD32) + kw + offA) * 4u);
#pragma unroll
            for (int p = 0; p < 4; p++) {
                unsigned b0, b1, b2, b3;
                LDSM4(b0, b1, b2, b3,
                      sB + ((uint32_t)((wn + p * 16) * LD32) + kw + offB) * 4u);
#pragma unroll
                for (int mi = 0; mi < 4; mi++) {
                    mmah(acc[mi][2 * p], af[mi], b0, b1);
                    mmah(acc[mi][2 * p + 1], af[mi], b2, b3);
                }
            }
        }
    }

    // epilogue
#pragma unroll
    for (int ni = 0; ni < 8; ni++) {
        int j = bn + wn + ni * 8 + 2 * lr;
        float b0 = bias[j], b1 = bias[j + 1];
        if (qkv_mode) {
            int plane = j / 768, pc = j - plane * 768;   // whole 128-tile in one plane
#pragma unroll
            for (int mi = 0; mi < 4; mi++) {
                int t = bm + wm + mi * 16 + lq;
#pragma unroll
                for (int hh = 0; hh < 2; hh++) {
                    int tt = t + 8 * hh;
                    float v0 = acc[mi][ni][2 * hh + 0] + b0;
                    float v1 = acc[mi][ni][2 * hh + 1] + b1;
                    if (plane == 0) {
                        *(unsigned*)(g_q + (size_t)tt * EMB_ + pc) =
                            packh(v0 * SCALE_Q, v1 * SCALE_Q);
                    } else if (plane == 1) {
                        *(unsigned*)(g_k + (size_t)tt * EMB_ + pc) = packh(v0, v1);
                    } else {
                        int b = tt >> 11, ntok = tt & 2047;
                        size_t base = ((size_t)b * EMB_ + pc) * SEQ + ntok;
                        g_vt[base] = __float2half_rn(v0);
                        g_vt[base + SEQ] = __float2half_rn(v1);
                    }
                }
            }
        } else {
#pragma unroll
            for (int mi = 0; mi < 4; mi++) {
                int t = bm + wm + mi * 16 + lq;
                *(float2*)(Cf + (size_t)t * EMB_ + j) =
                    make_float2(acc[mi][ni][0] + b0, acc[mi][ni][1] + b1);
                *(float2*)(Cf + (size_t)(t + 8) * EMB_ + j) =
                    make_float2(acc[mi][ni][2] + b0, acc[mi][ni][3] + b1);
            }
        }
    }
}

// -------- attention: fp16 FA2, warp-private 32 rows, LDSM frags -------------
#define AQ   128
#define AKT  64                             // tokens per iter
#define LQ32 52                             // 48 data + 4 pad
#define LK32 52
#define LV32 36                             // 32 data + 4 pad
#define OFFK 6656                           // sQ = 128*52
#define OFFV (OFFK + 2 * AKT * LK32)        // 13312
#define ATTW (OFFV + 2 * HDIM * LV32)       // 20224 w (80896 B)
#define NIT (SEQ / AKT)                     // 32

__device__ __forceinline__ void attn_issue(
    uint32_t smb, const __half* __restrict__ Kg, const __half* __restrict__ Vtg,
    int tid, int it)
{
    const int base = it * AKT;
    const int buf = it & 1;
    const uint32_t kb = smb + (uint32_t)(OFFK + buf * (AKT * LK32)) * 4u;
#pragma unroll
    for (int i = 0; i < 6; i++) {           // K: 64 rows x 12 x 16B
        int id = tid + 128 * i, r = id / 12, c4 = id - r * 12;
        cpa16(kb + (uint32_t)(r * LK32 + c4 * 4) * 4u,
              Kg + (size_t)(base + r) * EMB_ + c4 * 8);
    }
    const uint32_t vb = smb + (uint32_t)(OFFV + buf * (HDIM * LV32)) * 4u;
#pragma unroll
    for (int i = 0; i < 6; i++) {           // Vt: 96 rows x 8 x 16B
        int id = tid + 128 * i, r = id >> 3, c4 = id & 7;
        cpa16(vb + (uint32_t)(r * LV32 + c4 * 4) * 4u,
              Vtg + (size_t)r * SEQ + base + c4 * 8);
    }
    CP_COMMIT();
}

__global__ __launch_bounds__(128, 2) void attn4() {
    extern __shared__ unsigned smw[];
    const uint32_t smb = (uint32_t)__cvta_generic_to_shared(smw);

    const int bh = blockIdx.y;
    const int qb = blockIdx.x * AQ;
    const int b = bh >> 3, h = bh & 7;
    const int tid = threadIdx.x, w = tid >> 5, lane = tid & 31;
    const int lq = lane >> 2, lr = lane & 3;
    const int wr = w * 32;                  // warp-private row base

    // per-lane LDSM offsets (words)
    const uint32_t offAq = ((lane & 7) + ((lane >> 3) & 1) * 8) * LQ32 + (lane >> 4) * 4;
    const uint32_t offBk = ((lane & 7) + ((lane >> 4) & 1) * 8) * LK32 + ((lane >> 3) & 1) * 4;
    const uint32_t offBv = ((lane & 7) + ((lane >> 4) & 1) * 8) * LV32 + ((lane >> 3) & 1) * 4;

    const __half* Qg = g_q + (size_t)(b * SEQ + qb) * EMB_ + h * HDIM;
    const __half* Kg = g_k + (size_t)(b * SEQ) * EMB_ + h * HDIM;
    const __half* Vtg = g_vt + ((size_t)b * EMB_ + h * HDIM) * SEQ;

    // prologue: Q tile (128 rows x 12 x 16B = 1536 = 12*128) + KV stage 0
#pragma unroll
    for (int i = 0; i < 12; i++) {
        int id = tid + 128 * i, r = id / 12, c4 = id - r * 12;
        cpa16(smb + (uint32_t)(r * LQ32 + c4 * 4) * 4u,
              Qg + (size_t)r * EMB_ + c4 * 8);
    }
    attn_issue(smb, Kg, Vtg, tid, 0);

    float o[2][12][4];
#pragma unroll
    for (int i = 0; i < 2; i++)
#pragma unroll
        for (int j = 0; j < 12; j++)
#pragma unroll
            for (int q = 0; q < 4; q++) o[i][j][q] = 0.f;
    float rs[2][2] = {{0.f, 0.f}, {0.f, 0.f}};

    for (int it = 0; it < NIT; ++it) {
        CP_WAIT(0);
        __syncthreads();
        if (it + 1 < NIT) attn_issue(smb, Kg, Vtg, tid, it + 1);

        const uint32_t cKb = smb + (uint32_t)(OFFK + (it & 1) * (AKT * LK32)) * 4u;
        const uint32_t cVb = smb + (uint32_t)(OFFV + (it & 1) * (HDIM * LV32)) * 4u;

        // S[32x64] per warp = Q @ K^T  (6 k16 steps over HDIM=96)
        float s[2][8][4];
#pragma unroll
        for (int i = 0; i < 2; i++)
#pragma unroll
            for (int j = 0; j < 8; j++)
#pragma unroll
                for (int q = 0; q < 4; q++) s[i][j][q] = 0.f;

#pragma unroll
        for (int kk = 0; kk < 6; kk++) {
            const uint32_t kw = kk * 8;
            unsigned af[2][4];
#pragma unroll
            for (int mi = 0; mi < 2; mi++)
                LDSM4(af[mi][0], af[mi][1], af[mi][2], af[mi][3],
                      smb + ((uint32_t)((wr + mi * 16) * LQ32) + kw + offAq) * 4u);
#pragma unroll
            for (int p = 0; p < 4; p++) {
                unsigned b0, b1, b2, b3;
                LDSM4(b0, b1, b2, b3,
                      cKb + ((uint32_t)(p * 16 * LK32) + kw + offBk) * 4u);
                mmah(s[0][2 * p], af[0], b0, b1);
                mmah(s[1][2 * p], af[1], b0, b1);
                mmah(s[0][2 * p + 1], af[0], b2, b3);
                mmah(s[1][2 * p + 1], af[1], b2, b3);
            }
        }

        // P = fp16(2^S), packed in-place as PV A-frag halves; f32 row sums
        unsigned ph[2][8][2];
#pragma unroll
        for (int mi = 0; mi < 2; mi++)
#pragma unroll
            for (int ni = 0; ni < 8; ni++) {
                unsigned u0 = packh(ex2f(s[mi][ni][0]), ex2f(s[mi][ni][1]));
                unsigned u1 = packh(ex2f(s[mi][ni][2]), ex2f(s[mi][ni][3]));
                ph[mi][ni][0] = u0;
                ph[mi][ni][1] = u1;
                float2 f0 = __half22float2(*(__half2*)&u0);
                float2 f1 = __half22float2(*(__half2*)&u1);
                rs[mi][0] += f0.x + f0.y;
                rs[mi][1] += f1.x + f1.y;
            }

        // O += P @ V : A-frags ARE the packed c-frags (no shuffles)
#pragma unroll
        for (int j = 0; j < 4; j++) {
            unsigned af[2][4];
#pragma unroll
            for (int mi = 0; mi < 2; mi++) {
                af[mi][0] = ph[mi][2 * j][0];
                af[mi][1] = ph[mi][2 * j][1];
                af[mi][2] = ph[mi][2 * j + 1][0];
                af[mi][3] = ph[mi][2 * j + 1][1];
            }
            const uint32_t kw = j * 8;
#pragma unroll
            for (int p = 0; p < 6; p++) {
                unsigned b0, b1, b2, b3;
                LDSM4(b0, b1, b2, b3,
                      cVb + ((uint32_t)(p * 16 * LV32) + kw + offBv) * 4u);
                mmah(o[0][2 * p], af[0], b0, b1);
                mmah(o[1][2 * p], af[1], b0, b1);
                mmah(o[0][2 * p + 1], af[0], b2, b3);
                mmah(o[1][2 * p + 1], af[1], b2, b3);
            }
        }
    }

    // quad-reduce row sums (cols partitioned over lr within each quad)
#pragma unroll
    for (int mi = 0; mi < 2; mi++)
#pragma unroll
        for (int half = 0; half < 2; half++) {
            float v = rs[mi][half];
            v += __shfl_xor_sync(0xffffffffu, v, 1);
            v += __shfl_xor_sync(0xffffffffu, v, 2);
            rs[mi][half] = v;
        }

    // normalize, write ctx fp16
#pragma unroll
    for (int mi = 0; mi < 2; mi++) {
        int r0 = wr + mi * 16 + lq;
        float inv0 = 1.f / rs[mi][0];
        float inv1 = 1.f / rs[mi][1];
        size_t t0 = (size_t)(b * SEQ + qb + r0) * EMB_ + h * HDIM;
        size_t t1 = (size_t)(b * SEQ + qb + r0 + 8) * EMB_ + h * HDIM;
#pragma unroll
        for (int ni = 0; ni < 12; ni++) {
            int col = ni * 8 + 2 * lr;
            *(unsigned*)(g_ctx + t0 + col) = packh(o[mi][ni][0] * inv0,
                                                   o[mi][ni][1] * inv0);
            *(unsigned*)(g_ctx + t1 + col) = packh(o[mi][ni][2] * inv1,
                                                   o[mi][ni][3] * inv1);
        }
    }
}

// ---------------- launch -----------------------------------------------------
extern "C" void kernel_launch(void* const* d_in, const int* in_sizes, int n_in,
                              void* d_out, int out_size) {
    const float* x     = (const float*)d_in[0];
    const float* Wqkv  = (const float*)d_in[1];
    const float* bqkv  = (const float*)d_in[2];
    const float* Wproj = (const float*)d_in[3];
    const float* bproj = (const float*)d_in[4];
    float* out = (float*)d_out;

    void *pxh, *pw1, *pb1, *pw2, *pctx;
    cudaGetSymbolAddress(&pxh, g_xh);
    cudaGetSymbolAddress(&pw1, g_w1);
    cudaGetSymbolAddress(&pb1, g_b1);
    cudaGetSymbolAddress(&pw2, g_w2);
    cudaGetSymbolAddress(&pctx, g_ctx);

    const int gemm_smem = STG * STW * 4;   // 110592 B -> 2 CTAs/SM
    const int attn_smem = ATTW * 4;        // 80896 B  -> 2 CTAs/SM
    cudaFuncSetAttribute(gemm_h, cudaFuncAttributeMaxDynamicSharedMemorySize, gemm_smem);
    cudaFuncSetAttribute(attn4, cudaFuncAttributeMaxDynamicSharedMemorySize, attn_smem);

    // 0) prep: fp16 conversions (+ weight permute/transpose)
    cvth_k<<<(TOK * EMB_ / 4 + 255) / 256, 256>>>(
        (const float4*)x, (__half2*)pxh, TOK * EMB_ / 4);
    permw_k<<<(NQKV * (EMB_ / 4) + 255) / 256, 256>>>(Wqkv, bqkv);
    transw2_k<<<(EMB_ * (EMB_ / 4) + 255) / 256, 256>>>(Wproj);

    // 1) qkv = x @ Wqkv'^T + bqkv' -> q (scaled), k, v-transposed planes
    gemm_h<<<dim3(NQKV / BN, TOK / BM), 128, gemm_smem>>>(
        (const __half*)pxh, (const __half*)pw1, (const float*)pb1, nullptr, 1);

    // 2) attention -> ctx (fp16)
    attn4<<<dim3(SEQ / AQ, 32), 128, attn_smem>>>();

    // 3) out = ctx @ Wproj^T + bproj (fp32 out)
    gemm_h<<<dim3(EMB_ / BN, TOK / BM), 128, gemm_smem>>>(
        (const __half*)pctx, (const __half*)pw2, bproj, out, 0);
}